// round 3
// baseline (speedup 1.0000x reference)
#include <cuda_runtime.h>
#include <cuda_bf16.h>

// Problem constants (from reference)
#define C_L0 0.05f
#define C_D  0.0075f
#define C_DS 0.005f

// dy/ds for the 12 integrated components (r[3], R[9]); ux,uy constant.
// dr = R[:,2] (third column) = (y5, y8, y11)
// dR[i][0] = -uy*R[i][2]; dR[i][1] = ux*R[i][2]; dR[i][2] = uy*R[i][0] - ux*R[i][1]
__device__ __forceinline__ void ode_f(const float* __restrict__ y, float ux, float uy,
                                      float* __restrict__ d) {
    d[0] = y[5];
    d[1] = y[8];
    d[2] = y[11];
#pragma unroll
    for (int i = 0; i < 3; i++) {
        float r0 = y[3 + 3 * i];
        float r1 = y[4 + 3 * i];
        float r2 = y[5 + 3 * i];
        d[3 + 3 * i] = -uy * r2;
        d[4 + 3 * i] =  ux * r2;
        d[5 + 3 * i] = fmaf(uy, r0, -ux * r1);
    }
}

__device__ __forceinline__ void write_row(float* __restrict__ out, size_t row, int B, int b,
                                          const float* __restrict__ y, float ux, float uy) {
    // out[row, b, 0:14]; base byte offset is a multiple of 56 -> 8B aligned -> float2 ok
    float2* p = (float2*)(out + (row * (size_t)B + (size_t)b) * 14);
    p[0] = make_float2(y[0],  y[1]);
    p[1] = make_float2(y[2],  y[3]);
    p[2] = make_float2(y[4],  y[5]);
    p[3] = make_float2(y[6],  y[7]);
    p[4] = make_float2(y[8],  y[9]);
    p[5] = make_float2(y[10], y[11]);
    p[6] = make_float2(ux,    uy);
}

__global__ void __launch_bounds__(256)
ode_forward_kernel(const float* __restrict__ act, float* __restrict__ out, int B, int T) {
    int b = blockIdx.x * blockDim.x + threadIdx.x;
    if (b >= B) return;

    // Reference quirk: the action update at the END of loop iteration n uses
    // actions[:, n*3:(n+1)*3]; for n=0 that's columns 0:3 AGAIN. So BOTH
    // segments use actions[:, 0:3]; columns 3:6 are never consumed.
    float a0 = act[(size_t)b * 6 + 0];
    float a1 = act[(size_t)b * 6 + 1];
    float a2 = act[(size_t)b * 6 + 2];

    float l  = C_L0 + a0;
    float ux = a2 / (-(l * C_D));
    float uy = a1 / (l * C_D);
    int length = (int)floorf(l / C_DS);

    // y0: r=0, R=I
    float y[12];
    y[0] = 0.f; y[1] = 0.f; y[2]  = 0.f;
    y[3] = 1.f; y[4] = 0.f; y[5]  = 0.f;
    y[6] = 0.f; y[7] = 1.f; y[8]  = 0.f;
    y[9] = 0.f; y[10]= 0.f; y[11] = 1.f;

    const float h   = C_DS;
    const float h2  = 0.5f * C_DS;                 // matches f32(0.5*h)
    const float h6  = (float)(0.005 / 6.0);        // matches f32(h/6.0)

    int nsteps = min(length, T - 1);

#pragma unroll
    for (int seg = 0; seg < 2; seg++) {
        // t = 0 row (y0 of this segment, with ux/uy)
        write_row(out, (size_t)seg * T, B, b, y, ux, uy);

        for (int t = 1; t < T; t++) {
            if (t <= nsteps) {
                // RK4 with running accumulator; summation order matches
                // ((k1 + 2*k2) + 2*k3) + k4 (jax left-assoc).
                float k[12], acc[12], yt[12];
                ode_f(y, ux, uy, k);                      // k1
#pragma unroll
                for (int j = 0; j < 12; j++) {
                    acc[j] = k[j];
                    yt[j]  = fmaf(h2, k[j], y[j]);
                }
                ode_f(yt, ux, uy, k);                     // k2
#pragma unroll
                for (int j = 0; j < 12; j++) {
                    acc[j] = fmaf(2.f, k[j], acc[j]);
                    yt[j]  = fmaf(h2, k[j], y[j]);
                }
                ode_f(yt, ux, uy, k);                     // k3
#pragma unroll
                for (int j = 0; j < 12; j++) {
                    acc[j] = fmaf(2.f, k[j], acc[j]);
                    yt[j]  = fmaf(h, k[j], y[j]);
                }
                ode_f(yt, ux, uy, k);                     // k4
#pragma unroll
                for (int j = 0; j < 12; j++) {
                    y[j] = fmaf(h6, acc[j] + k[j], y[j]);
                }
            }
            // For t > nsteps the state is frozen: identical to sol[min(t,length)]
            write_row(out, (size_t)seg * T + t, B, b, y, ux, uy);
        }
    }
}

extern "C" void kernel_launch(void* const* d_in, const int* in_sizes, int n_in,
                              void* d_out, int out_size) {
    const float* actions = (const float*)d_in[0];
    float* out = (float*)d_out;

    int B = in_sizes[0] / 6;                 // 262144
    int T = out_size / (2 * B * 14);         // num time steps per segment (incl. t=0)

    int threads = 256;
    int blocks = (B + threads - 1) / threads;
    ode_forward_kernel<<<blocks, threads>>>(actions, out, B, T);
}

// round 4
// speedup vs baseline: 2.7131x; 2.7131x over previous
#include <cuda_runtime.h>
#include <cuda_bf16.h>

// Problem constants (from reference)
#define C_L0 0.05f
#define C_D  0.0075f
#define C_DS 0.005f

#define TPB 256          // batch elems per block == threads per block
#define SROW 15          // padded row stride in smem (gcd(15,32)=1 -> conflict-free)

// dy/ds for the 12 integrated components (r[3], R[9]); ux,uy constant.
__device__ __forceinline__ void ode_f(const float* __restrict__ y, float ux, float uy,
                                      float* __restrict__ d) {
    d[0] = y[5];
    d[1] = y[8];
    d[2] = y[11];
#pragma unroll
    for (int i = 0; i < 3; i++) {
        float r0 = y[3 + 3 * i];
        float r1 = y[4 + 3 * i];
        float r2 = y[5 + 3 * i];
        d[3 + 3 * i] = -uy * r2;
        d[4 + 3 * i] =  ux * r2;
        d[5 + 3 * i] = fmaf(uy, r0, -ux * r1);
    }
}

__global__ void __launch_bounds__(TPB)
ode_forward_kernel(const float* __restrict__ act, float* __restrict__ out, int B, int T) {
    __shared__ float sbuf[TPB * SROW];

    int b0 = blockIdx.x * TPB;
    int b  = b0 + threadIdx.x;
    bool active = (b < B);
    int nvalid   = min(TPB, B - b0);
    int rowfloats = nvalid * 14;

    // Reference quirk: the action update at the END of loop iteration n uses
    // actions[:, n*3:(n+1)*3]; for n=0 that's columns 0:3 AGAIN. So BOTH
    // segments use actions[:, 0:3]; columns 3:6 are never consumed.
    float a0 = 0.f, a1 = 0.f, a2 = 0.f;
    if (active) {
        a0 = act[(size_t)b * 6 + 0];
        a1 = act[(size_t)b * 6 + 1];
        a2 = act[(size_t)b * 6 + 2];
    }

    float l  = C_L0 + a0;
    float ux = a2 / (-(l * C_D));
    float uy = a1 / (l * C_D);
    int length = (int)floorf(l / C_DS);
    int nsteps = min(length, T - 1);

    // y0: r=0, R=I
    float y[12];
    y[0] = 0.f; y[1] = 0.f; y[2]  = 0.f;
    y[3] = 1.f; y[4] = 0.f; y[5]  = 0.f;
    y[6] = 0.f; y[7] = 1.f; y[8]  = 0.f;
    y[9] = 0.f; y[10]= 0.f; y[11] = 1.f;

    const float h   = C_DS;
    const float h2  = 0.5f * C_DS;                 // matches f32(0.5*h)
    const float h6  = (float)(0.005 / 6.0);        // matches f32(h/6.0)

    float* srow = sbuf + threadIdx.x * SROW;

#pragma unroll
    for (int seg = 0; seg < 2; seg++) {
        for (int t = 0; t < T; t++) {
            if (t >= 1 && t <= nsteps && active) {
                // RK4 accumulator form; summation order matches jax's
                // ((k1 + 2*k2) + 2*k3) + k4 left-assoc.
                float k[12], acc[12], yt[12];
                ode_f(y, ux, uy, k);                      // k1
#pragma unroll
                for (int j = 0; j < 12; j++) {
                    acc[j] = k[j];
                    yt[j]  = fmaf(h2, k[j], y[j]);
                }
                ode_f(yt, ux, uy, k);                     // k2
#pragma unroll
                for (int j = 0; j < 12; j++) {
                    acc[j] = fmaf(2.f, k[j], acc[j]);
                    yt[j]  = fmaf(h2, k[j], y[j]);
                }
                ode_f(yt, ux, uy, k);                     // k3
#pragma unroll
                for (int j = 0; j < 12; j++) {
                    acc[j] = fmaf(2.f, k[j], acc[j]);
                    yt[j]  = fmaf(h, k[j], y[j]);
                }
                ode_f(yt, ux, uy, k);                     // k4
#pragma unroll
                for (int j = 0; j < 12; j++) {
                    y[j] = fmaf(h6, acc[j] + k[j], y[j]);
                }
            }
            // For t > nsteps the state is frozen (== sol[min(t,length)])

            // Stage this time-row in smem, then write the block's contiguous
            // 14336B chunk with unit-stride stores (1 L1 line per wavefront).
            __syncthreads();   // previous row's copy must finish before overwrite
            if (active) {
#pragma unroll
                for (int j = 0; j < 12; j++) srow[j] = y[j];
                srow[12] = ux;
                srow[13] = uy;
            }
            __syncthreads();

            size_t base = ((size_t)(seg * T + t) * (size_t)B + (size_t)b0) * 14;
            for (int f = threadIdx.x; f < rowfloats; f += TPB) {
                int bi = f / 14;
                int e  = f - bi * 14;
                out[base + f] = sbuf[bi * SROW + e];
            }
        }
    }
}

extern "C" void kernel_launch(void* const* d_in, const int* in_sizes, int n_in,
                              void* d_out, int out_size) {
    const float* actions = (const float*)d_in[0];
    float* out = (float*)d_out;

    int B = in_sizes[0] / 6;                 // 262144
    int T = out_size / (2 * B * 14);         // time steps per segment (incl. t=0)

    int blocks = (B + TPB - 1) / TPB;
    ode_forward_kernel<<<blocks, TPB>>>(actions, out, B, T);
}

// round 6
// speedup vs baseline: 3.6444x; 1.3432x over previous
#include <cuda_runtime.h>
#include <cuda_bf16.h>

// Problem constants (from reference)
#define C_L0 0.05f
#define C_D  0.0075f
#define C_DS 0.005f

#define TPB 256          // batch elems per block == threads per block
#define ROWF (TPB * 14)  // floats per staged time-row (3584)

// dy/ds for the 12 integrated components (r[3], R[9]); ux,uy constant.
__device__ __forceinline__ void ode_f(const float* __restrict__ y, float ux, float uy,
                                      float* __restrict__ d) {
    d[0] = y[5];
    d[1] = y[8];
    d[2] = y[11];
#pragma unroll
    for (int i = 0; i < 3; i++) {
        float r0 = y[3 + 3 * i];
        float r1 = y[4 + 3 * i];
        float r2 = y[5 + 3 * i];
        d[3 + 3 * i] = -uy * r2;
        d[4 + 3 * i] =  ux * r2;
        d[5 + 3 * i] = fmaf(uy, r0, -ux * r1);
    }
}

__global__ void __launch_bounds__(TPB)
ode_forward_kernel(const float* __restrict__ act, float* __restrict__ out, int B, int T) {
    // Double-buffered, output-linear staging: one sync per row, identity copy.
    __shared__ float sbuf[2][ROWF];

    int b0 = blockIdx.x * TPB;
    int b  = b0 + threadIdx.x;
    bool active = (b < B);
    bool fullblk = (b0 + TPB <= B);
    int nvalid = min(TPB, B - b0);

    // Reference quirk: the action update at the END of loop iteration n uses
    // actions[:, n*3:(n+1)*3]; for n=0 that's columns 0:3 AGAIN. So BOTH
    // segments use actions[:, 0:3]; columns 3:6 are never consumed.
    float a0 = 0.f, a1 = 0.f, a2 = 0.f;
    if (active) {
        a0 = act[(size_t)b * 6 + 0];
        a1 = act[(size_t)b * 6 + 1];
        a2 = act[(size_t)b * 6 + 2];
    }

    float l  = C_L0 + a0;
    float ux = a2 / (-(l * C_D));
    float uy = a1 / (l * C_D);
    int length = (int)floorf(l / C_DS);
    int nsteps = min(length, T - 1);

    // y0: r=0, R=I
    float y[12];
    y[0] = 0.f; y[1] = 0.f; y[2]  = 0.f;
    y[3] = 1.f; y[4] = 0.f; y[5]  = 0.f;
    y[6] = 0.f; y[7] = 1.f; y[8]  = 0.f;
    y[9] = 0.f; y[10]= 0.f; y[11] = 1.f;

    const float h   = C_DS;
    const float h2  = 0.5f * C_DS;                 // matches f32(0.5*h)
    const float h6  = (float)(0.005 / 6.0);        // matches f32(h/6.0)

    int buf = 0;

#pragma unroll
    for (int seg = 0; seg < 2; seg++) {
        for (int t = 0; t < T; t++) {
            if (t >= 1 && t <= nsteps && active) {
                // RK4 accumulator form; summation order matches jax's
                // ((k1 + 2*k2) + 2*k3) + k4 left-assoc.
                float k[12], acc[12], yt[12];
                ode_f(y, ux, uy, k);                      // k1
#pragma unroll
                for (int j = 0; j < 12; j++) {
                    acc[j] = k[j];
                    yt[j]  = fmaf(h2, k[j], y[j]);
                }
                ode_f(yt, ux, uy, k);                     // k2
#pragma unroll
                for (int j = 0; j < 12; j++) {
                    acc[j] = fmaf(2.f, k[j], acc[j]);
                    yt[j]  = fmaf(h2, k[j], y[j]);
                }
                ode_f(yt, ux, uy, k);                     // k3
#pragma unroll
                for (int j = 0; j < 12; j++) {
                    acc[j] = fmaf(2.f, k[j], acc[j]);
                    yt[j]  = fmaf(h, k[j], y[j]);
                }
                ode_f(yt, ux, uy, k);                     // k4
#pragma unroll
                for (int j = 0; j < 12; j++) {
                    y[j] = fmaf(h6, acc[j] + k[j], y[j]);
                }
            }
            // For t > nsteps the state is frozen (== sol[min(t,length)])

            // Stage directly in output-linear layout: thread's row at tid*14.
            float* srow = &sbuf[buf][threadIdx.x * 14];
            if (active) {
#pragma unroll
                for (int j = 0; j < 12; j++) srow[j] = y[j];
                srow[12] = ux;
                srow[13] = uy;
            }
            __syncthreads();  // stage complete (also: buf's copy from 2 rows ago done)

            size_t base = ((size_t)(seg * T + t) * (size_t)B + (size_t)b0) * 14;
            if (fullblk) {
                // Identity float2 block copy: affine indices, no div/mod.
                const float2* s2 = (const float2*)&sbuf[buf][0];
                float2* o2 = (float2*)(out + base);
#pragma unroll
                for (int i = 0; i < 7; i++)
                    o2[threadIdx.x + i * TPB] = s2[threadIdx.x + i * TPB];
            } else {
                int rowfloats = nvalid * 14;
                for (int f = threadIdx.x; f < rowfloats; f += TPB)
                    out[base + f] = sbuf[buf][f];
            }
            buf ^= 1;
        }
    }
}

extern "C" void kernel_launch(void* const* d_in, const int* in_sizes, int n_in,
                              void* d_out, int out_size) {
    const float* actions = (const float*)d_in[0];
    float* out = (float*)d_out;

    int B = in_sizes[0] / 6;                 // 262144
    int T = out_size / (2 * B * 14);         // time steps per segment (incl. t=0)

    int blocks = (B + TPB - 1) / TPB;
    ode_forward_kernel<<<blocks, TPB>>>(actions, out, B, T);
}

// round 7
// speedup vs baseline: 3.7049x; 1.0166x over previous
#include <cuda_runtime.h>
#include <cuda_bf16.h>

// Problem constants (from reference)
#define C_L0 0.05f
#define C_D  0.0075f
#define C_DS 0.005f

#define TPB 256          // batch elems per block == threads per block
#define ROWF (TPB * 14)  // floats per staged time-row (3584)
#define ROWF4 (ROWF / 4) // float4s per row (896)

// dy/ds for the 12 integrated components (r[3], R[9]); ux,uy constant.
__device__ __forceinline__ void ode_f(const float* __restrict__ y, float ux, float uy,
                                      float* __restrict__ d) {
    d[0] = y[5];
    d[1] = y[8];
    d[2] = y[11];
#pragma unroll
    for (int i = 0; i < 3; i++) {
        float r0 = y[3 + 3 * i];
        float r1 = y[4 + 3 * i];
        float r2 = y[5 + 3 * i];
        d[3 + 3 * i] = -uy * r2;
        d[4 + 3 * i] =  ux * r2;
        d[5 + 3 * i] = fmaf(uy, r0, -ux * r1);
    }
}

__global__ void __launch_bounds__(TPB)
ode_forward_kernel(const float* __restrict__ act, float* __restrict__ out, int B, int T) {
    // Double-buffered, output-linear staging: one sync per row, identity copy.
    __shared__ __align__(16) float sbuf[2][ROWF];

    int b0 = blockIdx.x * TPB;
    int b  = b0 + threadIdx.x;
    bool active = (b < B);
    bool fullblk = (b0 + TPB <= B);
    int nvalid = min(TPB, B - b0);

    // Reference quirk: the action update at the END of loop iteration n uses
    // actions[:, n*3:(n+1)*3]; for n=0 that's columns 0:3 AGAIN. So BOTH
    // segments use actions[:, 0:3]; columns 3:6 are never consumed.
    float a0 = 0.f, a1 = 0.f, a2 = 0.f;
    if (active) {
        a0 = act[(size_t)b * 6 + 0];
        a1 = act[(size_t)b * 6 + 1];
        a2 = act[(size_t)b * 6 + 2];
    }

    float l  = C_L0 + a0;
    float ux = a2 / (-(l * C_D));
    float uy = a1 / (l * C_D);
    int length = (int)floorf(l / C_DS);
    int nsteps = min(length, T - 1);

    // y0: r=0, R=I
    float y[12];
    y[0] = 0.f; y[1] = 0.f; y[2]  = 0.f;
    y[3] = 1.f; y[4] = 0.f; y[5]  = 0.f;
    y[6] = 0.f; y[7] = 1.f; y[8]  = 0.f;
    y[9] = 0.f; y[10]= 0.f; y[11] = 1.f;

    const float h   = C_DS;
    const float h2  = 0.5f * C_DS;                 // matches f32(0.5*h)
    const float h6  = (float)(0.005 / 6.0);        // matches f32(h/6.0)

    int buf = 0;

#pragma unroll
    for (int seg = 0; seg < 2; seg++) {
        for (int t = 0; t < T; t++) {
            if (t >= 1 && t <= nsteps && active) {
                // RK4 accumulator form; summation order matches jax's
                // ((k1 + 2*k2) + 2*k3) + k4 left-assoc.
                float k[12], acc[12], yt[12];
                ode_f(y, ux, uy, k);                      // k1
#pragma unroll
                for (int j = 0; j < 12; j++) {
                    acc[j] = k[j];
                    yt[j]  = fmaf(h2, k[j], y[j]);
                }
                ode_f(yt, ux, uy, k);                     // k2
#pragma unroll
                for (int j = 0; j < 12; j++) {
                    acc[j] = fmaf(2.f, k[j], acc[j]);
                    yt[j]  = fmaf(h2, k[j], y[j]);
                }
                ode_f(yt, ux, uy, k);                     // k3
#pragma unroll
                for (int j = 0; j < 12; j++) {
                    acc[j] = fmaf(2.f, k[j], acc[j]);
                    yt[j]  = fmaf(h, k[j], y[j]);
                }
                ode_f(yt, ux, uy, k);                     // k4
#pragma unroll
                for (int j = 0; j < 12; j++) {
                    y[j] = fmaf(h6, acc[j] + k[j], y[j]);
                }
            }
            // For t > nsteps the state is frozen (== sol[min(t,length)])

            // Stage in output-linear layout with float2 STS (conflict-free:
            // bank(L,j) = (L*14 + 2j) % 32 is distinct within 16-lane phases).
            float2* srow = (float2*)&sbuf[buf][threadIdx.x * 14];
            if (active) {
                srow[0] = make_float2(y[0],  y[1]);
                srow[1] = make_float2(y[2],  y[3]);
                srow[2] = make_float2(y[4],  y[5]);
                srow[3] = make_float2(y[6],  y[7]);
                srow[4] = make_float2(y[8],  y[9]);
                srow[5] = make_float2(y[10], y[11]);
                srow[6] = make_float2(ux,    uy);
            }
            __syncthreads();  // stage complete (also: buf's copy from 2 rows ago done)

            size_t base = ((size_t)(seg * T + t) * (size_t)B + (size_t)b0) * 14;
            if (fullblk) {
                // Identity float4 block copy: 896 float4 = 3*256 + 128.
                const float4* s4 = (const float4*)&sbuf[buf][0];
                float4* o4 = (float4*)(out + base);
#pragma unroll
                for (int i = 0; i < 3; i++)
                    o4[threadIdx.x + i * TPB] = s4[threadIdx.x + i * TPB];
                if (threadIdx.x < (ROWF4 - 3 * TPB))
                    o4[threadIdx.x + 3 * TPB] = s4[threadIdx.x + 3 * TPB];
            } else {
                int rowfloats = nvalid * 14;
                for (int f = threadIdx.x; f < rowfloats; f += TPB)
                    out[base + f] = sbuf[buf][f];
            }
            buf ^= 1;
        }
    }
}

extern "C" void kernel_launch(void* const* d_in, const int* in_sizes, int n_in,
                              void* d_out, int out_size) {
    const float* actions = (const float*)d_in[0];
    float* out = (float*)d_out;

    int B = in_sizes[0] / 6;                 // 262144
    int T = out_size / (2 * B * 14);         // time steps per segment (incl. t=0)

    int blocks = (B + TPB - 1) / TPB;
    ode_forward_kernel<<<blocks, TPB>>>(actions, out, B, T);
}